// round 1
// baseline (speedup 1.0000x reference)
#include <cuda_runtime.h>
#include <cstdint>

// Problem constants (shapes are fixed by the dataset, but we derive E/nodes
// from the harness arguments where cheap).
#define D_FEAT 48
#define EDGES_PER_WARP 128

// ---------------------------------------------------------------------------
// Zero-init kernel: d_out is poisoned to 0xAA; rows with no incident edges
// must end up exactly 0. float4 stores, grid-stride.
// ---------------------------------------------------------------------------
__global__ void zero_out_kernel(float4* __restrict__ out, int n4) {
    int i = blockIdx.x * blockDim.x + threadIdx.x;
    if (i < n4) {
        out[i] = make_float4(0.f, 0.f, 0.f, 0.f);
    }
}

// ---------------------------------------------------------------------------
// Segmented-COO SpMM: rows are sorted, so each warp owns a contiguous chunk
// of EDGES_PER_WARP edges and accumulates messages for the current row in
// registers, flushing with atomicAdd only on row change / chunk boundary.
//
// Lane layout over D=48 features:
//   acc0: feature = lane        (all 32 lanes)
//   acc1: feature = 32 + lane   (lanes 0..15)
// => 2 coalesced LDG per edge for the x gather (128B + 64B).
//
// Edge metadata is loaded coalesced (one edge per lane per 32-edge window)
// and broadcast to the warp via __shfl_sync.
// ---------------------------------------------------------------------------
__global__ void __launch_bounds__(256) spmm_coo_kernel(
    const float* __restrict__ x,
    const int*   __restrict__ rows,
    const int*   __restrict__ cols,
    const float* __restrict__ vals,
    float*       __restrict__ out,
    int n_edges)
{
    const int warp_id = (blockIdx.x * blockDim.x + threadIdx.x) >> 5;
    const int lane    = threadIdx.x & 31;

    long e0 = (long)warp_id * EDGES_PER_WARP;
    if (e0 >= n_edges) return;
    const long e1 = min((long)n_edges, e0 + (long)EDGES_PER_WARP);

    int   cur = -1;     // current row being accumulated (warp-uniform)
    float a0  = 0.f;
    float a1  = 0.f;

    long base = e0;

    // Full 32-edge windows (the dataset divides exactly: 1.6M % 128 == 0).
    for (; base + 32 <= e1; base += 32) {
        const long e = base + lane;
        const int   rr = rows[e];
        const int   cc = cols[e];
        const float vv = vals[e];

        #pragma unroll
        for (int j = 0; j < 32; ++j) {
            const int   r = __shfl_sync(0xffffffffu, rr, j);
            const int   c = __shfl_sync(0xffffffffu, cc, j);
            const float v = __shfl_sync(0xffffffffu, vv, j);

            if (r != cur) {                       // warp-uniform branch
                if (cur >= 0) {
                    float* o = out + (size_t)cur * D_FEAT;
                    atomicAdd(o + lane, a0);
                    if (lane < 16) atomicAdd(o + 32 + lane, a1);
                }
                cur = r;
                a0 = 0.f;
                a1 = 0.f;
            }

            const float* xp = x + (size_t)c * D_FEAT;
            a0 += v * __ldg(xp + lane);
            if (lane < 16) a1 += v * __ldg(xp + 32 + lane);
        }
    }

    // Tail window (never taken for the dataset shape, kept for safety).
    for (; base < e1; ++base) {
        const int   r = rows[base];
        const int   c = cols[base];
        const float v = vals[base];
        if (r != cur) {
            if (cur >= 0) {
                float* o = out + (size_t)cur * D_FEAT;
                atomicAdd(o + lane, a0);
                if (lane < 16) atomicAdd(o + 32 + lane, a1);
            }
            cur = r;
            a0 = 0.f;
            a1 = 0.f;
        }
        const float* xp = x + (size_t)c * D_FEAT;
        a0 += v * __ldg(xp + lane);
        if (lane < 16) a1 += v * __ldg(xp + 32 + lane);
    }

    // Final flush.
    if (cur >= 0) {
        float* o = out + (size_t)cur * D_FEAT;
        atomicAdd(o + lane, a0);
        if (lane < 16) atomicAdd(o + 32 + lane, a1);
    }
}

// ---------------------------------------------------------------------------
// kernel_launch: inputs per metadata order: t, x, rows, cols, vals.
// ---------------------------------------------------------------------------
extern "C" void kernel_launch(void* const* d_in, const int* in_sizes, int n_in,
                              void* d_out, int out_size)
{
    // d_in[0] = t (unused)
    const float* x    = (const float*)d_in[1];
    const int*   rows = (const int*)  d_in[2];
    const int*   cols = (const int*)  d_in[3];
    const float* vals = (const float*)d_in[4];
    float*       out  = (float*)d_out;

    const int n_edges = in_sizes[4];

    // 1) zero the output (poisoned by harness)
    {
        const int n4 = out_size / 4;   // out_size = N_NODES * 48, divisible by 4
        const int threads = 256;
        const int blocks  = (n4 + threads - 1) / threads;
        zero_out_kernel<<<blocks, threads>>>((float4*)out, n4);
    }

    // 2) segmented SpMM
    {
        const int n_warps  = (n_edges + EDGES_PER_WARP - 1) / EDGES_PER_WARP;
        const int threads  = 256;                      // 8 warps / block
        const int blocks   = (n_warps * 32 + threads - 1) / threads;
        spmm_coo_kernel<<<blocks, threads>>>(x, rows, cols, vals, out, n_edges);
    }
}

// round 2
// speedup vs baseline: 1.3672x; 1.3672x over previous
#include <cuda_runtime.h>
#include <cstdint>

#define D_FEAT   48
#define N_NODES_MAX 100001   // dataset: 100000 nodes (+1 for row_ptr end)

// CSR row pointers built each launch from the sorted COO rows array.
__device__ int d_row_ptr[N_NODES_MAX + 1];

// ---------------------------------------------------------------------------
// Phase 1: row_ptr[r] = lower_bound(rows, rows + E, r).
// rows is sorted, 6.4MB -> lives in L2; 21 binary-search steps per thread,
// latency fully hidden by 100K-thread parallelism.
// ---------------------------------------------------------------------------
__global__ void build_row_ptr_kernel(const int* __restrict__ rows,
                                     int n_edges, int n_nodes)
{
    int r = blockIdx.x * blockDim.x + threadIdx.x;
    if (r > n_nodes) return;
    int lo = 0, hi = n_edges;
    while (lo < hi) {
        int mid = (lo + hi) >> 1;
        if (__ldg(rows + mid) < r) lo = mid + 1;
        else                       hi = mid;
    }
    d_row_ptr[r] = lo;
}

// ---------------------------------------------------------------------------
// Phase 2: warp-per-row CSR SpMV. No atomics, no row-change branches.
// Lane layout over D=48: acc0 covers f=lane (all lanes), acc1 covers
// f=32+lane (lanes 0..15) -> 2 coalesced LDGs per edge for the x gather.
// Edge metadata loaded coalesced by lanes 0..15 per 16-edge window, then
// broadcast with 2 SHFLs per edge. Unrolled 16-edge fast path lets ptxas
// front-batch the gather LDGs (high MLP).
// Every row stores unconditionally -> zero-init kernel not needed.
// ---------------------------------------------------------------------------
__global__ void __launch_bounds__(256) spmm_csr_warp_kernel(
    const float* __restrict__ x,
    const int*   __restrict__ cols,
    const float* __restrict__ vals,
    float*       __restrict__ out,
    int n_nodes)
{
    const int row  = (blockIdx.x * blockDim.x + threadIdx.x) >> 5;
    const int lane = threadIdx.x & 31;
    if (row >= n_nodes) return;

    const int s = d_row_ptr[row];
    const int e = d_row_ptr[row + 1];

    float a0 = 0.f;
    float a1 = 0.f;

    int base = s;
    while (base < e) {
        const int rem = e - base;
        const int cnt = rem < 16 ? rem : 16;

        int   c = 0;
        float v = 0.f;
        if (lane < cnt) {
            c = __ldg(cols + base + lane);
            v = __ldg(vals + base + lane);
        }

        if (cnt == 16) {
            #pragma unroll
            for (int j = 0; j < 16; ++j) {
                const int   cj = __shfl_sync(0xffffffffu, c, j);
                const float vj = __shfl_sync(0xffffffffu, v, j);
                const float* xp = x + (size_t)cj * D_FEAT;
                a0 += vj * __ldg(xp + lane);
                if (lane < 16) a1 += vj * __ldg(xp + 32 + lane);
            }
        } else {
            for (int j = 0; j < cnt; ++j) {
                const int   cj = __shfl_sync(0xffffffffu, c, j);
                const float vj = __shfl_sync(0xffffffffu, v, j);
                const float* xp = x + (size_t)cj * D_FEAT;
                a0 += vj * __ldg(xp + lane);
                if (lane < 16) a1 += vj * __ldg(xp + 32 + lane);
            }
        }
        base += cnt;
    }

    float* o = out + (size_t)row * D_FEAT;
    o[lane] = a0;
    if (lane < 16) o[32 + lane] = a1;
}

// ---------------------------------------------------------------------------
// kernel_launch: inputs per metadata order: t, x, rows, cols, vals.
// ---------------------------------------------------------------------------
extern "C" void kernel_launch(void* const* d_in, const int* in_sizes, int n_in,
                              void* d_out, int out_size)
{
    const float* x    = (const float*)d_in[1];
    const int*   rows = (const int*)  d_in[2];
    const int*   cols = (const int*)  d_in[3];
    const float* vals = (const float*)d_in[4];
    float*       out  = (float*)d_out;

    const int n_edges = in_sizes[4];
    const int n_nodes = out_size / D_FEAT;

    // Phase 1: CSR row pointers (n_nodes + 1 entries).
    {
        const int threads = 256;
        const int blocks  = (n_nodes + 1 + threads - 1) / threads;
        build_row_ptr_kernel<<<blocks, threads>>>(rows, n_edges, n_nodes);
    }

    // Phase 2: warp-per-row SpMM (writes every output element; no zero pass).
    {
        const int threads = 256;                       // 8 warps/block
        const int warps   = n_nodes;
        const int blocks  = (warps * 32 + threads - 1) / threads;
        spmm_csr_warp_kernel<<<blocks, threads>>>(x, cols, vals, out, n_nodes);
    }
}

// round 3
// speedup vs baseline: 1.6324x; 1.1939x over previous
#include <cuda_runtime.h>
#include <cstdint>

#define D_FEAT      48
#define N_NODES_MAX 100001

// CSR row pointers built each launch from the sorted COO rows array.
__device__ int d_row_ptr[N_NODES_MAX + 1];

// ---------------------------------------------------------------------------
// Phase 1: row_ptr[r] = lower_bound(rows, rows + E, r). rows sorted; 6.4MB
// lives in L2; ~17 binary-search steps, hidden by 100K-thread parallelism.
// ---------------------------------------------------------------------------
__global__ void build_row_ptr_kernel(const int* __restrict__ rows,
                                     int n_edges, int n_nodes)
{
    int r = blockIdx.x * blockDim.x + threadIdx.x;
    if (r > n_nodes) return;
    int lo = 0, hi = n_edges;
    while (lo < hi) {
        int mid = (lo + hi) >> 1;
        if (__ldg(rows + mid) < r) lo = mid + 1;
        else                       hi = mid;
    }
    d_row_ptr[r] = lo;
}

// ---------------------------------------------------------------------------
// Phase 2: half-warp-per-row CSR SpMM.
//   warp w -> rows {2w, 2w+1}; lanes [0,16) -> row A, lanes [16,32) -> row B.
//   Within a half: lanes sub=0..11 each own 4 features (float4), sub=12..15 idle.
//   Per edge (per half): uniform __ldg of (col, val) [L1-broadcast], one
//   LDG.128 gather of x[col], 4 FFMAs. One warp iteration advances BOTH rows.
//   No shfl, no windowing, no atomics. Every row stores unconditionally, so
//   no zero-init pass is needed.
// ---------------------------------------------------------------------------
__global__ void __launch_bounds__(256, 6) spmm_csr_halfwarp_kernel(
    const float* __restrict__ x,
    const int*   __restrict__ cols,
    const float* __restrict__ vals,
    float*       __restrict__ out,
    int n_nodes)
{
    const int warp_id = (blockIdx.x * blockDim.x + threadIdx.x) >> 5;
    const int lane    = threadIdx.x & 31;
    const int half    = lane >> 4;          // 0: row A, 1: row B
    const int sub     = lane & 15;          // lane within half
    const bool active = sub < 12;           // 12 lanes x float4 = 48 features

    const int row = warp_id * 2 + half;
    if (row >= n_nodes) return;

    const int s = d_row_ptr[row];
    const int e = d_row_ptr[row + 1];

    float ax = 0.f, ay = 0.f, az = 0.f, aw = 0.f;

    const int foff = sub * 4;               // feature offset owned by this lane

    #pragma unroll 4
    for (int i = s; i < e; ++i) {
        const int   c = __ldg(cols + i);    // uniform within half -> L1 broadcast
        const float v = __ldg(vals + i);
        if (active) {
            const float4 xv = *reinterpret_cast<const float4*>(
                x + (size_t)c * D_FEAT + foff);     // LDG.E.128
            ax += v * xv.x;
            ay += v * xv.y;
            az += v * xv.z;
            aw += v * xv.w;
        }
    }

    if (active) {
        float4* o = reinterpret_cast<float4*>(out + (size_t)row * D_FEAT + foff);
        *o = make_float4(ax, ay, az, aw);   // STG.E.128 (zeros for empty rows)
    }
}

// ---------------------------------------------------------------------------
// kernel_launch: inputs per metadata order: t, x, rows, cols, vals.
// ---------------------------------------------------------------------------
extern "C" void kernel_launch(void* const* d_in, const int* in_sizes, int n_in,
                              void* d_out, int out_size)
{
    const float* x    = (const float*)d_in[1];
    const int*   rows = (const int*)  d_in[2];
    const int*   cols = (const int*)  d_in[3];
    const float* vals = (const float*)d_in[4];
    float*       out  = (float*)d_out;

    const int n_edges = in_sizes[4];
    const int n_nodes = out_size / D_FEAT;

    // Phase 1: CSR row pointers.
    {
        const int threads = 256;
        const int blocks  = (n_nodes + 1 + threads - 1) / threads;
        build_row_ptr_kernel<<<blocks, threads>>>(rows, n_edges, n_nodes);
    }

    // Phase 2: half-warp-per-row SpMM (2 rows per warp).
    {
        const int threads = 256;                           // 8 warps/block
        const int warps   = (n_nodes + 1) / 2;
        const int blocks  = (warps * 32 + threads - 1) / threads;
        spmm_csr_halfwarp_kernel<<<blocks, threads>>>(x, cols, vals, out, n_nodes);
    }
}